// round 5
// baseline (speedup 1.0000x reference)
#include <cuda_runtime.h>
#include <cuda_bf16.h>

// Embedding gather: out[t, :] = e[token_ids[t], :]
// token_ids: [2*4096] int32, e: [32000, 1024] fp32, out: [8192, 1024] fp32
//
// One CTA per token row. 256 threads x float4 = 1024 floats = one row.
// Fully coalesced 128-bit loads and stores; pure HBM-bound copy.

#define DIM 1024
#define THREADS 256   // 256 * 4 floats = 1024 = DIM

__global__ void __launch_bounds__(THREADS)
embedding_gather_kernel(const int* __restrict__ token_ids,
                        const float4* __restrict__ e,   // [32000, DIM/4]
                        float4* __restrict__ out)       // [n_tok, DIM/4]
{
    const int row = blockIdx.x;             // token position 0..n_tok-1
    const int tok = __ldg(&token_ids[row]); // uniform per block (broadcast sector)
    const int c   = threadIdx.x;            // 0..255, float4 column

    const long long src = (long long)tok * (DIM / 4) + c;
    const long long dst = (long long)row * (DIM / 4) + c;
    out[dst] = __ldg(&e[src]);
}

extern "C" void kernel_launch(void* const* d_in, const int* in_sizes, int n_in,
                              void* d_out, int out_size)
{
    // Robust to input ordering: token_ids is the small int32 buffer,
    // e is the large fp32 table (32000*1024 elements).
    const int* token_ids;
    const float4* e;
    if (n_in >= 2 && in_sizes[0] > in_sizes[1]) {
        e         = (const float4*)d_in[0];
        token_ids = (const int*)d_in[1];
    } else {
        token_ids = (const int*)d_in[0];
        e         = (const float4*)d_in[1];
    }
    float4* out = (float4*)d_out;

    // Rows derived from output size: out is [n_tok, DIM] fp32.
    const int n_tok = out_size / DIM;       // 8192
    embedding_gather_kernel<<<n_tok, THREADS>>>(token_ids, e, out);
}

// round 6
// speedup vs baseline: 1.0901x; 1.0901x over previous
#include <cuda_runtime.h>
#include <cuda_bf16.h>

// Embedding gather: out[t, :] = e[token_ids[t], :]
// token_ids: [8192] int32, e: [32000, 1024] fp32, out: [8192, 1024] fp32
//
// R5 showed latency-bound behavior (all pipes <31%, issue 12%): one LDG in
// flight per thread. Fix: batch 8 rows per CTA, front-load all 8 independent
// row LDG.128s (MLP=8/thread) before storing.

#define DIM4     256   // DIM / 4 float4s per row
#define THREADS  256   // one float4 column per thread
#define ROWS     8     // rows per CTA

__global__ void __launch_bounds__(THREADS)
embedding_gather_kernel(const int* __restrict__ token_ids,
                        const float4* __restrict__ e,    // [32000, DIM4]
                        float4* __restrict__ out,        // [n_tok, DIM4]
                        int n_tok)
{
    const int row0 = blockIdx.x * ROWS;
    const int c    = threadIdx.x;

    // 1) Batch the index loads (uniform per block -> broadcast sectors).
    int toks[ROWS];
#pragma unroll
    for (int r = 0; r < ROWS; r++) {
        int row = row0 + r;
        toks[r] = (row < n_tok) ? __ldg(&token_ids[row]) : 0;
    }

    // 2) Front-issue all 8 independent row loads (MLP=8 per thread).
    float4 v[ROWS];
#pragma unroll
    for (int r = 0; r < ROWS; r++)
        v[r] = __ldg(&e[(long long)toks[r] * DIM4 + c]);

    // 3) Drain to the output.
#pragma unroll
    for (int r = 0; r < ROWS; r++) {
        int row = row0 + r;
        if (row < n_tok)
            out[(long long)row * DIM4 + c] = v[r];
    }
}

extern "C" void kernel_launch(void* const* d_in, const int* in_sizes, int n_in,
                              void* d_out, int out_size)
{
    // Robust to input ordering: token_ids is the small int32 buffer,
    // e is the large fp32 table.
    const int* token_ids;
    const float4* e;
    if (n_in >= 2 && in_sizes[0] > in_sizes[1]) {
        e         = (const float4*)d_in[0];
        token_ids = (const int*)d_in[1];
    } else {
        token_ids = (const int*)d_in[0];
        e         = (const float4*)d_in[1];
    }
    float4* out = (float4*)d_out;

    const int n_tok = out_size / (DIM4 * 4);            // 8192
    const int grid  = (n_tok + ROWS - 1) / ROWS;        // 1024
    embedding_gather_kernel<<<grid, THREADS>>>(token_ids, e, out, n_tok);
}

// round 7
// speedup vs baseline: 1.1194x; 1.0269x over previous
#include <cuda_runtime.h>
#include <cuda_bf16.h>
#include <cstdint>

// Embedding gather via bulk-async TMA: out[t,:] = e[token_ids[t],:]
// Each CTA (32 threads, only thread 0 active) copies ROWS=4 embedding rows
// (4 KB each) GMEM -> SMEM via cp.async.bulk + mbarrier, then SMEM -> GMEM
// via cp.async.bulk bulk_group. No per-lane LDG/STG at all.

#define ROW_BYTES 4096          // 1024 fp32
#define ROWS      4             // rows per CTA
#define DIM       1024

__device__ __forceinline__ uint32_t smem_u32(const void* p) {
    return (uint32_t)__cvta_generic_to_shared(p);
}

__global__ void __launch_bounds__(32)
embedding_tma_kernel(const int* __restrict__ token_ids,
                     const char* __restrict__ e,     // [32000, 4096 B]
                     char* __restrict__ out,         // [n_tok, 4096 B]
                     int n_tok)
{
    __shared__ alignas(128) char buf[ROWS * ROW_BYTES];
    __shared__ alignas(8)   uint64_t mbar;

    if (threadIdx.x != 0) return;     // single-thread CTA control; TMA moves data

    const int row0 = blockIdx.x * ROWS;
    if (row0 >= n_tok) return;
    const int nr = (n_tok - row0 < ROWS) ? (n_tok - row0) : ROWS;

    // --- init mbarrier, make it visible to the async proxy ---
    const uint32_t mb = smem_u32(&mbar);
    asm volatile("mbarrier.init.shared.b64 [%0], 1;" :: "r"(mb) : "memory");
    asm volatile("fence.proxy.async.shared::cta;" ::: "memory");

    // --- expect all bytes, then issue the gather loads back-to-back ---
    const uint32_t tx = (uint32_t)nr * ROW_BYTES;
    asm volatile("mbarrier.arrive.expect_tx.shared.b64 _, [%0], %1;"
                 :: "r"(mb), "r"(tx) : "memory");

    #pragma unroll
    for (int r = 0; r < ROWS; r++) {
        if (r >= nr) break;
        const int tok = __ldg(&token_ids[row0 + r]);
        const uint64_t src =
            (uint64_t)__cvta_generic_to_global(e) + (uint64_t)tok * ROW_BYTES;
        const uint32_t dst = smem_u32(buf + r * ROW_BYTES);
        asm volatile(
            "cp.async.bulk.shared::cta.global.mbarrier::complete_tx::bytes "
            "[%0], [%1], %2, [%3];"
            :: "r"(dst), "l"(src), "r"((uint32_t)ROW_BYTES), "r"(mb)
            : "memory");
    }

    // --- wait for all loads (phase 0) ---
    {
        uint32_t done;
        asm volatile(
            "{\n\t.reg .pred p;\n\t"
            "mbarrier.try_wait.parity.shared.b64 p, [%1], 0;\n\t"
            "selp.b32 %0, 1, 0, p;\n\t}"
            : "=r"(done) : "r"(mb) : "memory");
        while (!done) {
            asm volatile(
                "{\n\t.reg .pred p;\n\t"
                "mbarrier.try_wait.parity.shared.b64 p, [%1], 0, 0x989680;\n\t"
                "selp.b32 %0, 1, 0, p;\n\t}"
                : "=r"(done) : "r"(mb) : "memory");
        }
    }

    // --- bulk store each row to the output ---
    #pragma unroll
    for (int r = 0; r < ROWS; r++) {
        if (r >= nr) break;
        const uint64_t dst =
            (uint64_t)__cvta_generic_to_global(out) +
            (uint64_t)(row0 + r) * ROW_BYTES;
        const uint32_t src = smem_u32(buf + r * ROW_BYTES);
        asm volatile(
            "cp.async.bulk.global.shared::cta.bulk_group [%0], [%1], %2;"
            :: "l"(dst), "r"(src), "r"((uint32_t)ROW_BYTES)
            : "memory");
    }
    asm volatile("cp.async.bulk.commit_group;" ::: "memory");
    asm volatile("cp.async.bulk.wait_group 0;" ::: "memory");
}

extern "C" void kernel_launch(void* const* d_in, const int* in_sizes, int n_in,
                              void* d_out, int out_size)
{
    // Robust to input ordering: token_ids is the small int32 buffer,
    // e is the large fp32 table.
    const int* token_ids;
    const char* e;
    if (n_in >= 2 && in_sizes[0] > in_sizes[1]) {
        e         = (const char*)d_in[0];
        token_ids = (const int*)d_in[1];
    } else {
        token_ids = (const int*)d_in[0];
        e         = (const char*)d_in[1];
    }
    char* out = (char*)d_out;

    const int n_tok = out_size / DIM;                   // 8192
    const int grid  = (n_tok + ROWS - 1) / ROWS;        // 2048
    embedding_tma_kernel<<<grid, 32>>>(token_ids, e, out, n_tok);
}